// round 13
// baseline (speedup 1.0000x reference)
#include <cuda_runtime.h>
#include <cuda_fp16.h>
#include <cstdint>

#define NN 16384
#define CC 64
#define JJ 16
#define OO 128
#define RSP 144                 // proj row stride bytes (128 data + 16 pad; 9 quads)
#define RS2 272                 // staging row stride bytes
#define PBUF (64 * RSP)         // 9216
#define SBUF (64 * RS2)         // 17408

// smem layout (bytes)
#define SM_ADJ 0                // 1024 ints = 4096
#define SM_P   4096             // 4 x PBUF = 36864
#define SM_STG 40960            // 2 x SBUF = 34816
#define SMEMTOT 75776

// A fragments pre-baked (fp16 pairs), m16n8k16 layout:
// word i = ((((j*4+c)*4+mi)*2+mh)*32 + lane)*4 + aidx
__device__ unsigned char g_Wf[JJ * 4 * 4 * 2 * 32 * 16];   // 256 KB

__global__ void wprep(const float* __restrict__ w) {
    int i = blockIdx.x * 256 + threadIdx.x;      // 65536 words
    int aidx = i & 3;
    int lane = (i >> 2) & 31;
    int mh   = (i >> 7) & 1;
    int mi   = (i >> 8) & 3;
    int c    = (i >> 10) & 3;
    int j    = i >> 12;
    int g = lane >> 2, tg = lane & 3;
    int o  = mi * 32 + mh * 16 + (aidx & 1) * 8 + g;
    int k0 = c * 16 + (aidx >> 1) * 8 + 2 * tg;
    float v0 = w[(o * CC + k0) * JJ + j];
    float v1 = w[(o * CC + k0 + 1) * JJ + j];
    uint32_t r; asm("cvt.rn.f16x2.f32 %0, %1, %2;" : "=r"(r) : "f"(v1), "f"(v0));  // low <- v0
    ((uint32_t*)g_Wf)[i] = r;
}

__device__ __forceinline__ uint32_t smem_u32(const void* p) {
    uint32_t a; asm("{ .reg .u64 t; cvta.to.shared.u64 t, %1; cvt.u32.u64 %0, t; }" : "=r"(a) : "l"(p));
    return a;
}
__device__ __forceinline__ uint32_t pkh(float flo, float fhi) {   // low half <- flo
    uint32_t r; asm("cvt.rn.f16x2.f32 %0, %1, %2;" : "=r"(r) : "f"(fhi), "f"(flo));
    return r;
}
__device__ __forceinline__ void ldm4(uint32_t* r, uint32_t addr) {
    asm volatile("ldmatrix.sync.aligned.m8n8.x4.shared.b16 {%0,%1,%2,%3}, [%4];"
        : "=r"(r[0]), "=r"(r[1]), "=r"(r[2]), "=r"(r[3]) : "r"(addr));
}
__device__ __forceinline__ void mma16816(float* c, const uint32_t* a, uint32_t b0, uint32_t b1) {
    asm volatile("mma.sync.aligned.m16n8k16.row.col.f32.f16.f16.f32 "
        "{%0,%1,%2,%3},{%4,%5,%6,%7},{%8,%9},{%0,%1,%2,%3};"
        : "+f"(c[0]), "+f"(c[1]), "+f"(c[2]), "+f"(c[3])
        : "r"(a[0]), "r"(a[1]), "r"(a[2]), "r"(a[3]), "r"(b0), "r"(b1));
}
__device__ __forceinline__ void cp16(uint32_t dst, const void* src) {
    asm volatile("cp.async.cg.shared.global [%0], [%1], 16;" :: "r"(dst), "l"(src));
}

__global__ __launch_bounds__(256, 2) void sconv_kernel(
    const float* __restrict__ x, const int* __restrict__ adj, float* __restrict__ out)
{
    extern __shared__ unsigned char S[];
    const uint32_t sb = smem_u32(S);
    const int tid = threadIdx.x, lid = tid & 31, wid = tid >> 5;
    const int b  = blockIdx.x >> 8;               // 512 blocks: 256 per batch
    const int n0 = (blockIdx.x & 255) << 6;       // 64 points per block
    const float* xb = x + (size_t)b * NN * CC;

    const int p_ = tid >> 2, l = tid & 3;         // builder: 4 lanes/point, 16 ch each

    // consumer mapping: 4 m-warps x 2 n-warps; warp tile m32 x n32
    const int mi = wid & 3;
    const int nw = (wid >> 2) * 32;
    const int g8 = lid >> 3, r8 = lid & 7;
    const uint32_t boff = (uint32_t)((nw + r8 + 8 * (g8 >> 1)) * RSP + (g8 & 1) * 16);
    const int r4 = lid >> 2, c4 = lid & 3;

    int* adjS = (int*)S;
    {
        int base = (b * NN + n0) * 17;
        #pragma unroll
        for (int i = 0; i < 4; i++) {
            int idx = tid + 256 * i;              // 1024 ints (skip self col 0)
            adjS[idx] = adj[base + (idx >> 4) * 17 + 1 + (idx & 15)];
        }
    }

    // center values hoisted to registers (16 ch per builder lane)
    float ce[16];
    {
        const float4* cp_ = (const float4*)(xb + (size_t)(n0 + p_) * CC + l * 16);
        #pragma unroll
        for (int q = 0; q < 4; q++) {
            float4 v = cp_[q];
            ce[4*q+0] = v.x; ce[4*q+1] = v.y; ce[4*q+2] = v.z; ce[4*q+3] = v.w;
        }
    }
    __syncthreads();   // adjS ready

    auto gatherA = [&](int j) {
        int gi = adjS[p_ * 16 + j];
        const float* src = xb + (size_t)gi * CC + l * 16;
        uint32_t dst = sb + SM_STG + (j & 1) * SBUF + p_ * RS2 + l * 64;
        #pragma unroll
        for (int q = 0; q < 4; q++) cp16(dst + q * 16, src + q * 4);
    };
    auto buildP = [&](int j) {
        const float4* st = (const float4*)(S + SM_STG + (j & 1) * SBUF + p_ * RS2 + l * 64);
        float d[16]; float ssq = 0.f;
        #pragma unroll
        for (int q = 0; q < 4; q++) {
            float4 nv = st[q];
            d[4*q+0] = nv.x - ce[4*q+0]; d[4*q+1] = nv.y - ce[4*q+1];
            d[4*q+2] = nv.z - ce[4*q+2]; d[4*q+3] = nv.w - ce[4*q+3];
        }
        #pragma unroll
        for (int q = 0; q < 16; q++) ssq = fmaf(d[q], d[q], ssq);
        ssq += __shfl_xor_sync(0xffffffffu, ssq, 1);
        ssq += __shfl_xor_sync(0xffffffffu, ssq, 2);
        float s = rsqrtf(2.0f * ssq);             // 1/(sqrt2*||diff||)
        uint32_t h[8];
        #pragma unroll
        for (int q = 0; q < 8; q++) h[q] = pkh(d[2*q] * s, d[2*q+1] * s);
        unsigned char* P = S + SM_P + (j & 3) * PBUF + p_ * RSP + l * 32;
        ((uint4*)P)[0] = ((uint4*)h)[0];
        ((uint4*)P)[1] = ((uint4*)h)[1];
    };

    float acc[32], mx[32];
    #pragma unroll
    for (int i = 0; i < 32; i++) mx[i] = 0.f;     // relu+max -> init 0

    auto mmaJ = [&](int j) {
        #pragma unroll
        for (int i = 0; i < 32; i++) acc[i] = 0.f;
        const uint32_t Pb = sb + SM_P + (j & 3) * PBUF;
        #pragma unroll
        for (int c = 0; c < 4; c++) {
            // A: 2 LDG.128 from fragment-layout gmem (L1-hot)
            const unsigned char* ab = g_Wf + ((size_t)(((j * 4 + c) * 4 + mi) * 2) << 9) + (lid << 4);
            uint32_t a0[4], a1[4];
            *(uint4*)a0 = *(const uint4*)(ab);
            *(uint4*)a1 = *(const uint4*)(ab + 512);
            // B: 2 ldmatrix.x4 -> n32 x k16
            uint32_t bh[8];
            ldm4(bh,     Pb + boff + 32 * c);
            ldm4(bh + 4, Pb + boff + 16 * RSP + 32 * c);
            #pragma unroll
            for (int q = 0; q < 2; q++) {
                #pragma unroll
                for (int h2 = 0; h2 < 2; h2++) {
                    int nt = 2 * q + h2;
                    uint32_t b0 = bh[4*q + 2*h2], b1 = bh[4*q + 2*h2 + 1];
                    mma16816(&acc[nt * 4],      a0, b0, b1);
                    mma16816(&acc[16 + nt * 4], a1, b0, b1);
                }
            }
        }
        #pragma unroll
        for (int i = 0; i < 32; i++) mx[i] = fmaxf(mx[i], acc[i]);
    };

    // prologue: gather+build j=0,1 into proj[0], proj[1]
    gatherA(0);
    asm volatile("cp.async.commit_group;");
    gatherA(1);
    asm volatile("cp.async.commit_group;");
    asm volatile("cp.async.wait_group 1;" ::: "memory");
    buildP(0);
    asm volatile("cp.async.wait_group 0;" ::: "memory");
    buildP(1);
    __syncthreads();

    for (int jp = 0; jp < 8; jp++) {
        const int j0 = 2 * jp;
        if (jp < 7) {
            gatherA(j0 + 2);
            asm volatile("cp.async.commit_group;");
            gatherA(j0 + 3);
            asm volatile("cp.async.commit_group;");
        }
        mmaJ(j0);
        if (jp < 7) {
            asm volatile("cp.async.wait_group 1;" ::: "memory");   // gather(j0+2) done
            buildP(j0 + 2);
        }
        mmaJ(j0 + 1);
        if (jp < 7) {
            asm volatile("cp.async.wait_group 0;" ::: "memory");   // gather(j0+3) done
            buildP(j0 + 3);
        }
        __syncthreads();
    }

    // write out[b][o][n]
    {
        const int m0 = mi * 32;
        #pragma unroll
        for (int mh = 0; mh < 2; mh++) {
            #pragma unroll
            for (int nt = 0; nt < 4; nt++) {
                float* a = &mx[mh * 16 + nt * 4];
                int ncol = n0 + nw + nt * 8 + 2 * c4;
                int o1 = m0 + 16 * mh + r4;
                *(float2*)(out + (size_t)(b * OO + o1) * NN + ncol)     = make_float2(a[0], a[1]);
                *(float2*)(out + (size_t)(b * OO + o1 + 8) * NN + ncol) = make_float2(a[2], a[3]);
            }
        }
    }
}

extern "C" void kernel_launch(void* const* d_in, const int* in_sizes, int n_in,
                              void* d_out, int out_size) {
    const float* x   = (const float*)d_in[0];
    const int*   adj = (const int*)d_in[1];
    const float* w   = (const float*)d_in[2];
    float* out = (float*)d_out;

    cudaFuncSetAttribute(sconv_kernel, cudaFuncAttributeMaxDynamicSharedMemorySize, SMEMTOT);
    wprep<<<256, 256>>>(w);
    sconv_kernel<<<512, 256, SMEMTOT>>>(x, adj, out);
}

// round 14
// speedup vs baseline: 1.2243x; 1.2243x over previous
#include <cuda_runtime.h>
#include <cuda_fp16.h>
#include <cstdint>

#define NN 16384
#define CC 64
#define JJ 16
#define OO 128
#define RSP 144                 // proj row stride bytes (128 data + 16 pad; 9 quads)
#define RSH 144                 // fp16 staging row stride bytes (128 data + 16 pad)
#define PBUF (64 * RSP)         // 9216
#define SBUF (64 * RSH)         // 9216

// smem layout (bytes)
#define SM_ADJ 0                // 1024 ints = 4096
#define SM_P   4096             // 2 x PBUF = 18432
#define SM_STG 22528            // 1 x SBUF = 9216
#define SMEMTOT 31744

// fp16 copy of x: [b][n][c]
__device__ __half g_xh[2 * NN * CC];            // 4 MB

__global__ void xprep(const float* __restrict__ x) {
    int i = blockIdx.x * 256 + threadIdx.x;     // 1M float2 pairs
    float2 v = ((const float2*)x)[i];
    uint32_t r; asm("cvt.rn.f16x2.f32 %0, %1, %2;" : "=r"(r) : "f"(v.y), "f"(v.x));
    ((uint32_t*)g_xh)[i] = r;
}

// A fragments pre-baked (fp16 pairs), m16n8k16 layout:
// word i = ((((j*4+c)*4+mi)*2+mh)*32 + lane)*4 + aidx
__device__ unsigned char g_Wf[JJ * 4 * 4 * 2 * 32 * 16];   // 256 KB

__global__ void wprep(const float* __restrict__ w) {
    int i = blockIdx.x * 256 + threadIdx.x;      // 65536 words
    int aidx = i & 3;
    int lane = (i >> 2) & 31;
    int mh   = (i >> 7) & 1;
    int mi   = (i >> 8) & 3;
    int c    = (i >> 10) & 3;
    int j    = i >> 12;
    int g = lane >> 2, tg = lane & 3;
    int o  = mi * 32 + mh * 16 + (aidx & 1) * 8 + g;
    int k0 = c * 16 + (aidx >> 1) * 8 + 2 * tg;
    float v0 = w[(o * CC + k0) * JJ + j];
    float v1 = w[(o * CC + k0 + 1) * JJ + j];
    uint32_t r; asm("cvt.rn.f16x2.f32 %0, %1, %2;" : "=r"(r) : "f"(v1), "f"(v0));  // low <- v0
    ((uint32_t*)g_Wf)[i] = r;
}

__device__ __forceinline__ uint32_t smem_u32(const void* p) {
    uint32_t a; asm("{ .reg .u64 t; cvta.to.shared.u64 t, %1; cvt.u32.u64 %0, t; }" : "=r"(a) : "l"(p));
    return a;
}
__device__ __forceinline__ uint32_t pkh(float flo, float fhi) {   // low half <- flo
    uint32_t r; asm("cvt.rn.f16x2.f32 %0, %1, %2;" : "=r"(r) : "f"(fhi), "f"(flo));
    return r;
}
__device__ __forceinline__ void ldm4(uint32_t* r, uint32_t addr) {
    asm volatile("ldmatrix.sync.aligned.m8n8.x4.shared.b16 {%0,%1,%2,%3}, [%4];"
        : "=r"(r[0]), "=r"(r[1]), "=r"(r[2]), "=r"(r[3]) : "r"(addr));
}
__device__ __forceinline__ void mma16816(float* c, const uint32_t* a, uint32_t b0, uint32_t b1) {
    asm volatile("mma.sync.aligned.m16n8k16.row.col.f32.f16.f16.f32 "
        "{%0,%1,%2,%3},{%4,%5,%6,%7},{%8,%9},{%0,%1,%2,%3};"
        : "+f"(c[0]), "+f"(c[1]), "+f"(c[2]), "+f"(c[3])
        : "r"(a[0]), "r"(a[1]), "r"(a[2]), "r"(a[3]), "r"(b0), "r"(b1));
}
__device__ __forceinline__ void cp16(uint32_t dst, const void* src) {
    asm volatile("cp.async.cg.shared.global [%0], [%1], 16;" :: "r"(dst), "l"(src));
}

__global__ __launch_bounds__(256, 2) void sconv_kernel(
    const float* __restrict__ x, const int* __restrict__ adj, float* __restrict__ out)
{
    extern __shared__ unsigned char S[];
    const uint32_t sb = smem_u32(S);
    const int tid = threadIdx.x, lid = tid & 31, wid = tid >> 5;
    const int b  = blockIdx.x >> 8;               // 512 blocks: 256 per batch
    const int n0 = (blockIdx.x & 255) << 6;       // 64 points per block
    const float* xb = x + (size_t)b * NN * CC;
    const __half* xhb = g_xh + (size_t)b * NN * CC;

    const int p_ = tid >> 2, l = tid & 3;         // builder: 4 lanes/point, 16 ch each

    // consumer mapping: 4 m-warps x 2 n-warps; warp tile m32 x n32
    const int mi = wid & 3;
    const int nw = (wid >> 2) * 32;
    const int g8 = lid >> 3, r8 = lid & 7;
    const uint32_t boff = (uint32_t)((nw + r8 + 8 * (g8 >> 1)) * RSP + (g8 & 1) * 16);
    const int r4 = lid >> 2, c4 = lid & 3;

    int* adjS = (int*)S;
    {
        int base = (b * NN + n0) * 17;
        #pragma unroll
        for (int i = 0; i < 4; i++) {
            int idx = tid + 256 * i;              // 1024 ints (skip self col 0)
            adjS[idx] = adj[base + (idx >> 4) * 17 + 1 + (idx & 15)];
        }
    }

    // center values (exact fp32) hoisted to registers: 16 ch per builder lane
    float ce[16];
    {
        const float4* cp_ = (const float4*)(xb + (size_t)(n0 + p_) * CC + l * 16);
        #pragma unroll
        for (int q = 0; q < 4; q++) {
            float4 v = cp_[q];
            ce[4*q+0] = v.x; ce[4*q+1] = v.y; ce[4*q+2] = v.z; ce[4*q+3] = v.w;
        }
    }
    __syncthreads();   // adjS ready

    auto gatherA = [&](int j) {                   // fp16 gather: 32 B per lane
        int gi = adjS[p_ * 16 + j];
        const __half* src = xhb + (size_t)gi * CC + l * 16;
        uint32_t dst = sb + SM_STG + p_ * RSH + l * 32;
        cp16(dst,      src);
        cp16(dst + 16, src + 8);
    };
    auto buildP = [&](int j) {
        uint32_t hst[8];
        {
            uint32_t a0 = sb + SM_STG + p_ * RSH + l * 32;
            asm volatile("ld.shared.v4.b32 {%0,%1,%2,%3}, [%4];"
                : "=r"(hst[0]), "=r"(hst[1]), "=r"(hst[2]), "=r"(hst[3]) : "r"(a0));
            asm volatile("ld.shared.v4.b32 {%0,%1,%2,%3}, [%4];"
                : "=r"(hst[4]), "=r"(hst[5]), "=r"(hst[6]), "=r"(hst[7]) : "r"(a0 + 16));
        }
        float d[16]; float ssq = 0.f;
        #pragma unroll
        for (int q = 0; q < 8; q++) {
            float2 f = __half22float2(*(const __half2*)&hst[q]);
            d[2*q]   = f.x - ce[2*q];
            d[2*q+1] = f.y - ce[2*q+1];
        }
        #pragma unroll
        for (int q = 0; q < 16; q++) ssq = fmaf(d[q], d[q], ssq);
        ssq += __shfl_xor_sync(0xffffffffu, ssq, 1);
        ssq += __shfl_xor_sync(0xffffffffu, ssq, 2);
        float s = rsqrtf(2.0f * ssq);             // 1/(sqrt2*||diff||)
        uint32_t h[8];
        #pragma unroll
        for (int q = 0; q < 8; q++) h[q] = pkh(d[2*q] * s, d[2*q+1] * s);
        unsigned char* P = S + SM_P + (j & 1) * PBUF + p_ * RSP + l * 32;
        ((uint4*)P)[0] = ((uint4*)h)[0];
        ((uint4*)P)[1] = ((uint4*)h)[1];
    };

    float acc[32], mx[32];
    #pragma unroll
    for (int i = 0; i < 32; i++) mx[i] = 0.f;     // relu+max -> init 0

    gatherA(0);
    asm volatile("cp.async.commit_group;");
    asm volatile("cp.async.wait_group 0;" ::: "memory");
    buildP(0);
    __syncthreads();

    for (int j = 0; j < JJ; j++) {
        if (j + 1 < JJ) {
            gatherA(j + 1);
            asm volatile("cp.async.commit_group;");
        }
        #pragma unroll
        for (int i = 0; i < 32; i++) acc[i] = 0.f;
        const uint32_t Pb = sb + SM_P + (j & 1) * PBUF;
        #pragma unroll
        for (int c = 0; c < 4; c++) {
            // A: 2 LDG.128 from fragment-layout gmem (L1-hot)
            const unsigned char* ab = g_Wf + ((size_t)(((j * 4 + c) * 4 + mi) * 2) << 9) + (lid << 4);
            uint32_t a0[4], a1[4];
            *(uint4*)a0 = *(const uint4*)(ab);
            *(uint4*)a1 = *(const uint4*)(ab + 512);
            // B: 2 ldmatrix.x4 -> n32 x k16
            uint32_t bh[8];
            ldm4(bh,     Pb + boff + 32 * c);
            ldm4(bh + 4, Pb + boff + 16 * RSP + 32 * c);
            #pragma unroll
            for (int q = 0; q < 2; q++) {
                #pragma unroll
                for (int h2 = 0; h2 < 2; h2++) {
                    int nt = 2 * q + h2;
                    uint32_t b0 = bh[4*q + 2*h2], b1 = bh[4*q + 2*h2 + 1];
                    mma16816(&acc[nt * 4],      a0, b0, b1);
                    mma16816(&acc[16 + nt * 4], a1, b0, b1);
                }
            }
        }
        #pragma unroll
        for (int i = 0; i < 32; i++) mx[i] = fmaxf(mx[i], acc[i]);

        if (j + 1 < JJ) {
            asm volatile("cp.async.wait_group 0;" ::: "memory");
            buildP(j + 1);
        }
        __syncthreads();
    }

    // write out[b][o][n]
    {
        const int m0 = mi * 32;
        #pragma unroll
        for (int mh = 0; mh < 2; mh++) {
            #pragma unroll
            for (int nt = 0; nt < 4; nt++) {
                float* a = &mx[mh * 16 + nt * 4];
                int ncol = n0 + nw + nt * 8 + 2 * c4;
                int o1 = m0 + 16 * mh + r4;
                *(float2*)(out + (size_t)(b * OO + o1) * NN + ncol)     = make_float2(a[0], a[1]);
                *(float2*)(out + (size_t)(b * OO + o1 + 8) * NN + ncol) = make_float2(a[2], a[3]);
            }
        }
    }
}

extern "C" void kernel_launch(void* const* d_in, const int* in_sizes, int n_in,
                              void* d_out, int out_size) {
    const float* x   = (const float*)d_in[0];
    const int*   adj = (const int*)d_in[1];
    const float* w   = (const float*)d_in[2];
    float* out = (float*)d_out;

    cudaFuncSetAttribute(sconv_kernel, cudaFuncAttributeMaxDynamicSharedMemorySize, SMEMTOT);
    xprep<<<4096, 256>>>(x);
    wprep<<<256, 256>>>(w);
    sconv_kernel<<<512, 256, SMEMTOT>>>(x, adj, out);
}

// round 15
// speedup vs baseline: 1.2360x; 1.0096x over previous
#include <cuda_runtime.h>
#include <cuda_fp16.h>
#include <cstdint>

#define NN 16384
#define CC 64
#define JJ 16
#define OO 128
#define RSP 144                 // proj row stride bytes (128 data + 16 pad; 9 quads)
#define PBUF (64 * RSP)         // 9216

// smem layout (bytes)
#define SM_ADJ 0                // 1024 ints = 4096
#define SM_P   4096             // 2 x PBUF = 18432
#define SMEMTOT 22528

// fp16 copy of x: [b][n][c]
__device__ __half g_xh[2 * NN * CC];            // 4 MB
// A fragments pre-baked (fp16 pairs), m16n8k16 layout:
// word i = ((((j*4+c)*4+mi)*2+mh)*32 + lane)*4 + aidx
__device__ unsigned char g_Wf[JJ * 4 * 4 * 2 * 32 * 16];   // 256 KB

// fused prep: blocks [0,1024) convert x (4 words/thread); blocks [1024,1280) bake W
__global__ void prep(const float* __restrict__ x, const float* __restrict__ w) {
    int bx = blockIdx.x, tid = threadIdx.x;
    if (bx < 1024) {
        int i = bx * 256 + tid;                  // 262144 threads, 4 uint32 out each
        const float4* src = (const float4*)x + i * 2;
        float4 v0 = src[0], v1 = src[1];
        uint4 o;
        asm("cvt.rn.f16x2.f32 %0, %1, %2;" : "=r"(o.x) : "f"(v0.y), "f"(v0.x));
        asm("cvt.rn.f16x2.f32 %0, %1, %2;" : "=r"(o.y) : "f"(v0.w), "f"(v0.z));
        asm("cvt.rn.f16x2.f32 %0, %1, %2;" : "=r"(o.z) : "f"(v1.y), "f"(v1.x));
        asm("cvt.rn.f16x2.f32 %0, %1, %2;" : "=r"(o.w) : "f"(v1.w), "f"(v1.z));
        ((uint4*)g_xh)[i] = o;
    } else {
        int i = (bx - 1024) * 256 + tid;         // 65536 words
        int aidx = i & 3;
        int lane = (i >> 2) & 31;
        int mh   = (i >> 7) & 1;
        int mi   = (i >> 8) & 3;
        int c    = (i >> 10) & 3;
        int j    = i >> 12;
        int g = lane >> 2, tg = lane & 3;
        int o  = mi * 32 + mh * 16 + (aidx & 1) * 8 + g;
        int k0 = c * 16 + (aidx >> 1) * 8 + 2 * tg;
        float v0 = w[(o * CC + k0) * JJ + j];
        float v1 = w[(o * CC + k0 + 1) * JJ + j];
        uint32_t r; asm("cvt.rn.f16x2.f32 %0, %1, %2;" : "=r"(r) : "f"(v1), "f"(v0));
        ((uint32_t*)g_Wf)[i] = r;
    }
}

__device__ __forceinline__ uint32_t smem_u32(const void* p) {
    uint32_t a; asm("{ .reg .u64 t; cvta.to.shared.u64 t, %1; cvt.u32.u64 %0, t; }" : "=r"(a) : "l"(p));
    return a;
}
__device__ __forceinline__ uint32_t pkh(float flo, float fhi) {   // low half <- flo
    uint32_t r; asm("cvt.rn.f16x2.f32 %0, %1, %2;" : "=r"(r) : "f"(fhi), "f"(flo));
    return r;
}
__device__ __forceinline__ void ldm4(uint32_t* r, uint32_t addr) {
    asm volatile("ldmatrix.sync.aligned.m8n8.x4.shared.b16 {%0,%1,%2,%3}, [%4];"
        : "=r"(r[0]), "=r"(r[1]), "=r"(r[2]), "=r"(r[3]) : "r"(addr));
}
__device__ __forceinline__ void mma16816(float* c, const uint32_t* a, uint32_t b0, uint32_t b1) {
    asm volatile("mma.sync.aligned.m16n8k16.row.col.f32.f16.f16.f32 "
        "{%0,%1,%2,%3},{%4,%5,%6,%7},{%8,%9},{%0,%1,%2,%3};"
        : "+f"(c[0]), "+f"(c[1]), "+f"(c[2]), "+f"(c[3])
        : "r"(a[0]), "r"(a[1]), "r"(a[2]), "r"(a[3]), "r"(b0), "r"(b1));
}

__global__ __launch_bounds__(256, 2) void sconv_kernel(
    const float* __restrict__ x, const int* __restrict__ adj, float* __restrict__ out)
{
    extern __shared__ unsigned char S[];
    const uint32_t sb = smem_u32(S);
    const int tid = threadIdx.x, lid = tid & 31, wid = tid >> 5;
    const int b  = blockIdx.x >> 8;               // 512 blocks: 256 per batch
    const int n0 = (blockIdx.x & 255) << 6;       // 64 points per block
    const float* xb = x + (size_t)b * NN * CC;
    const __half* xhb = g_xh + (size_t)b * NN * CC;

    const int p_ = tid >> 2, l = tid & 3;         // builder: 4 lanes/point, 16 ch each

    // consumer mapping: 4 m-warps x 2 n-warps; warp tile m32 x n32
    const int mi = wid & 3;
    const int nw = (wid >> 2) * 32;
    const int g8 = lid >> 3, r8 = lid & 7;
    const uint32_t boff = (uint32_t)((nw + r8 + 8 * (g8 >> 1)) * RSP + (g8 & 1) * 16);
    const int r4 = lid >> 2, c4 = lid & 3;

    int* adjS = (int*)S;
    {
        int base = (b * NN + n0) * 17;
        #pragma unroll
        for (int i = 0; i < 4; i++) {
            int idx = tid + 256 * i;              // 1024 ints (skip self col 0)
            adjS[idx] = adj[base + (idx >> 4) * 17 + 1 + (idx & 15)];
        }
    }

    // center values (exact fp32) hoisted to registers: 16 ch per builder lane
    float ce[16];
    {
        const float4* cp_ = (const float4*)(xb + (size_t)(n0 + p_) * CC + l * 16);
        #pragma unroll
        for (int q = 0; q < 4; q++) {
            float4 v = cp_[q];
            ce[4*q+0] = v.x; ce[4*q+1] = v.y; ce[4*q+2] = v.z; ce[4*q+3] = v.w;
        }
    }
    __syncthreads();   // adjS ready

    // direct fp16 gather into registers (2 x LDG.128 per thread)
    uint4 pf0, pf1;
    auto prefetch = [&](int j) {
        int gi = adjS[p_ * 16 + j];
        const uint4* src = (const uint4*)(xhb + (size_t)gi * CC + l * 16);
        pf0 = src[0];
        pf1 = src[1];
    };
    auto buildP = [&](int j) {
        const uint32_t* hs0 = (const uint32_t*)&pf0;
        const uint32_t* hs1 = (const uint32_t*)&pf1;
        float d[16]; float ssq = 0.f;
        #pragma unroll
        for (int q = 0; q < 4; q++) {
            float2 f = __half22float2(*(const __half2*)&hs0[q]);
            d[2*q]   = f.x - ce[2*q];
            d[2*q+1] = f.y - ce[2*q+1];
        }
        #pragma unroll
        for (int q = 0; q < 4; q++) {
            float2 f = __half22float2(*(const __half2*)&hs1[q]);
            d[8+2*q]   = f.x - ce[8+2*q];
            d[8+2*q+1] = f.y - ce[8+2*q+1];
        }
        #pragma unroll
        for (int q = 0; q < 16; q++) ssq = fmaf(d[q], d[q], ssq);
        ssq += __shfl_xor_sync(0xffffffffu, ssq, 1);
        ssq += __shfl_xor_sync(0xffffffffu, ssq, 2);
        float s = rsqrtf(2.0f * ssq);             // 1/(sqrt2*||diff||)
        uint32_t h[8];
        #pragma unroll
        for (int q = 0; q < 8; q++) h[q] = pkh(d[2*q] * s, d[2*q+1] * s);
        unsigned char* P = S + SM_P + (j & 1) * PBUF + p_ * RSP + l * 32;
        ((uint4*)P)[0] = ((uint4*)h)[0];
        ((uint4*)P)[1] = ((uint4*)h)[1];
    };

    float acc[32], mx[32];
    #pragma unroll
    for (int i = 0; i < 32; i++) mx[i] = 0.f;     // relu+max -> init 0

    prefetch(0);
    buildP(0);
    __syncthreads();

    for (int j = 0; j < JJ; j++) {
        if (j + 1 < JJ) prefetch(j + 1);          // LDG issues here; consumed after mma
        #pragma unroll
        for (int i = 0; i < 32; i++) acc[i] = 0.f;
        const uint32_t Pb = sb + SM_P + (j & 1) * PBUF;
        #pragma unroll
        for (int c = 0; c < 4; c++) {
            // A: 2 LDG.128 from fragment-layout gmem (L1-hot)
            const unsigned char* ab = g_Wf + ((size_t)(((j * 4 + c) * 4 + mi) * 2) << 9) + (lid << 4);
            uint32_t a0[4], a1[4];
            *(uint4*)a0 = *(const uint4*)(ab);
            *(uint4*)a1 = *(const uint4*)(ab + 512);
            // B: 2 ldmatrix.x4 -> n32 x k16
            uint32_t bh[8];
            ldm4(bh,     Pb + boff + 32 * c);
            ldm4(bh + 4, Pb + boff + 16 * RSP + 32 * c);
            #pragma unroll
            for (int q = 0; q < 2; q++) {
                #pragma unroll
                for (int h2 = 0; h2 < 2; h2++) {
                    int nt = 2 * q + h2;
                    uint32_t b0 = bh[4*q + 2*h2], b1 = bh[4*q + 2*h2 + 1];
                    mma16816(&acc[nt * 4],      a0, b0, b1);
                    mma16816(&acc[16 + nt * 4], a1, b0, b1);
                }
            }
        }
        #pragma unroll
        for (int i = 0; i < 32; i++) mx[i] = fmaxf(mx[i], acc[i]);

        if (j + 1 < JJ) buildP(j + 1);
        __syncthreads();
    }

    // write out[b][o][n]
    {
        const int m0 = mi * 32;
        #pragma unroll
        for (int mh = 0; mh < 2; mh++) {
            #pragma unroll
            for (int nt = 0; nt < 4; nt++) {
                float* a = &mx[mh * 16 + nt * 4];
                int ncol = n0 + nw + nt * 8 + 2 * c4;
                int o1 = m0 + 16 * mh + r4;
                *(float2*)(out + (size_t)(b * OO + o1) * NN + ncol)     = make_float2(a[0], a[1]);
                *(float2*)(out + (size_t)(b * OO + o1 + 8) * NN + ncol) = make_float2(a[2], a[3]);
            }
        }
    }
}

extern "C" void kernel_launch(void* const* d_in, const int* in_sizes, int n_in,
                              void* d_out, int out_size) {
    const float* x   = (const float*)d_in[0];
    const int*   adj = (const int*)d_in[1];
    const float* w   = (const float*)d_in[2];
    float* out = (float*)d_out;

    cudaFuncSetAttribute(sconv_kernel, cudaFuncAttributeMaxDynamicSharedMemorySize, SMEMTOT);
    prep<<<1280, 256>>>(x, w);
    sconv_kernel<<<512, 256, SMEMTOT>>>(x, adj, out);
}